// round 14
// baseline (speedup 1.0000x reference)
#include <cuda_runtime.h>
#include <cuda_bf16.h>
#include <cstdint>

#define C 32
#define EPSBN 1e-5f
#define KTAP 125
#define MAXN 500000
#define MAXBLK 8192
#define NSTG 4
#define MB 128                 // voxels per block
#define CTHREADS 128           // 4 warps x 32 voxels

typedef unsigned long long ull;

// smem layout (bytes)
#define OFF_X   0                       // 4 stages x 16384 (x tiles, swizzled 128B rows)
#define OFF_W   65536                   // 2 x 4096 W double-buffer
#define OFF_RED 73728                   // 4 warps x 32 cols x 2 floats
#define SMEM_SZ 74752                   // 73 KB -> 3 CTAs/SM

// ---- device scratch ----
__device__ __align__(16) unsigned char g_xhl[(size_t)MAXN * 128];  // [N][hi 64B | lo 64B]
__device__ __align__(16) unsigned char g_whl[KTAP * 4096];         // [K][cin][hi 64B | lo 64B]
__device__ __align__(16) float g_Wt[KTAP * C * C];                 // fallback
__device__ float g_part[MAXBLK * 2 * C];
__device__ float g_part2[64 * 2 * C];
__device__ float g_mean[C];
__device__ float g_rstd[C];

// ---- PTX helpers ----
__device__ __forceinline__ void cp_async16z(uint32_t dst, const void* src, uint32_t sz) {
    asm volatile("cp.async.cg.shared.global [%0], [%1], 16, %2;" :: "r"(dst), "l"(src), "r"(sz));
}
__device__ __forceinline__ void cp_commit() { asm volatile("cp.async.commit_group;"); }
template <int N_> __device__ __forceinline__ void cp_wait() {
    asm volatile("cp.async.wait_group %0;" :: "n"(N_));
}
__device__ __forceinline__ void ldsm4(uint32_t* r, uint32_t a) {
    asm volatile("ldmatrix.sync.aligned.m8n8.x4.shared.b16 {%0,%1,%2,%3}, [%4];"
                 : "=r"(r[0]), "=r"(r[1]), "=r"(r[2]), "=r"(r[3]) : "r"(a));
}
__device__ __forceinline__ void ldsm4t(uint32_t* r, uint32_t a) {
    asm volatile("ldmatrix.sync.aligned.m8n8.x4.trans.shared.b16 {%0,%1,%2,%3}, [%4];"
                 : "=r"(r[0]), "=r"(r[1]), "=r"(r[2]), "=r"(r[3]) : "r"(a));
}
__device__ __forceinline__ void mma16816(float* c, const uint32_t* a, const uint32_t* b) {
    asm volatile("mma.sync.aligned.m16n8k16.row.col.f32.bf16.bf16.f32 "
                 "{%0,%1,%2,%3}, {%4,%5,%6,%7}, {%8,%9}, {%0,%1,%2,%3};"
                 : "+f"(c[0]), "+f"(c[1]), "+f"(c[2]), "+f"(c[3])
                 : "r"(a[0]), "r"(a[1]), "r"(a[2]), "r"(a[3]), "r"(b[0]), "r"(b[1]));
}
__device__ __forceinline__ ull fma2(ull a, ull b, ull c) {
    ull d; asm("fma.rn.f32x2 %0, %1, %2, %3;" : "=l"(d) : "l"(a), "l"(b), "l"(c)); return d;
}
union F2U { float2 f; ull u; };

// ---------------- pre-convert x -> [hi|lo] bf16 rows ----------------
__global__ void convert_x(const float* __restrict__ x, int n) {
    int v = blockIdx.x * blockDim.x + threadIdx.x;
    if (v >= n) return;
    const float* xr = x + (size_t)v * C;
    __nv_bfloat16 hb[C], lb[C];
#pragma unroll
    for (int i = 0; i < C; i++) {
        float f = xr[i];
        __nv_bfloat16 h = __float2bfloat16(f);
        hb[i] = h;
        lb[i] = __float2bfloat16(f - __bfloat162float(h));
    }
    uint4* dst = (uint4*)(g_xhl + (size_t)v * 128);
    const uint4* hp = (const uint4*)hb;
    const uint4* lp = (const uint4*)lb;
#pragma unroll
    for (int q = 0; q < 4; q++) dst[q] = hp[q];
#pragma unroll
    for (int q = 0; q < 4; q++) dst[4 + q] = lp[q];
}

// ---------------- pre-convert W [K][CIN][COUT] -> [K][cin][hi|lo] ----------------
__global__ void convert_w(const float* __restrict__ W, int total) {
    int i = blockIdx.x * blockDim.x + threadIdx.x;
    if (i >= total) return;
    int k = i / (C * C), r = i % (C * C);
    int cin = r >> 5, cout = r & 31;
    float f = W[i];
    __nv_bfloat16 h = __float2bfloat16(f);
    __nv_bfloat16 l = __float2bfloat16(f - __bfloat162float(h));
    __nv_bfloat16* row = (__nv_bfloat16*)(g_whl + (size_t)k * 4096 + cin * 128);
    row[cout] = h;
    row[32 + cout] = l;
}

// ---------------- mma sparse conv (4-stage x ring + 2-buf W via LDG/STS) ----------------
template <int KT>
__global__ __launch_bounds__(CTHREADS, 3) void conv_mma(
    const int* __restrict__ nbr, const float* __restrict__ bconv,
    float* __restrict__ out, int n)
{
    extern __shared__ __align__(16) unsigned char smem[];
    const uint32_t sb = (uint32_t)__cvta_generic_to_shared(smem);
    const int tid = threadIdx.x, warp = tid >> 5, lane = tid & 31;
    const int vb = blockIdx.x * MB;
    const int vg = vb + tid;               // this thread's gather voxel
    const bool vok = vg < n;
    const int q = lane >> 3, rl = lane & 7;   // ldmatrix addressing
    const int g = lane >> 2, tq = lane & 3;   // mma fragment coords
    const int* nrow = nbr + (size_t)(vok ? vg : 0) * KT;

    // this thread's two W chunk addresses (fixed swizzled STS targets per buffer)
    const int cc0 = tid, cc1 = tid + 128;
    const uint32_t wsts0 = (uint32_t)((cc0 >> 3) * 128 + ((((cc0 & 7) ^ ((cc0 >> 3) & 7))) << 4));
    const uint32_t wsts1 = (uint32_t)((cc1 >> 3) * 128 + ((((cc1 & 7) ^ ((cc1 >> 3) & 7))) << 4));

    float acc[2][4][4];
#pragma unroll
    for (int a = 0; a < 2; a++)
#pragma unroll
        for (int b = 0; b < 4; b++)
#pragma unroll
            for (int c = 0; c < 4; c++) acc[a][b][c] = 0.f;

    int nidx[NSTG];

    auto FETCH = [&](int tt) {
        nidx[tt & 3] = vok ? __ldg(nrow + tt) : -1;
    };
    auto ISSUE = [&](int tt) {
        int s = tt & 3;
        int id = nidx[s];
        uint32_t sz = (id >= 0) ? 16u : 0u;
        const unsigned char* src = g_xhl + (size_t)(id < 0 ? 0 : id) * 128;
        uint32_t xdst = sb + OFF_X + s * 16384 + tid * 128;
#pragma unroll
        for (int j = 0; j < 8; j++)
            cp_async16z(xdst + (uint32_t)(((j ^ (lane & 7)) << 4)), src + j * 16, sz);
    };
    auto WLDG = [&](int tt, uint4* w) {
        const uint4* p = (const uint4*)(g_whl + (size_t)tt * 4096);
        w[0] = __ldg(p + cc0);
        w[1] = __ldg(p + cc1);
    };
    auto WSTS = [&](int buf, const uint4* w) {
        uint32_t base = sb + OFF_W + buf * 4096;
        *(uint4*)(smem + (base - sb) + wsts0) = w[0];
        *(uint4*)(smem + (base - sb) + wsts1) = w[1];
    };
    auto COMPUTE = [&](int tt) {
        int s = tt & 3;
        uint32_t xb = sb + OFF_X + s * 16384;
        uint32_t wb = sb + OFF_W + (tt & 1) * 4096;
        uint32_t wf[2][2][4][2];
#pragma unroll
        for (int part = 0; part < 2; part++)
#pragma unroll
            for (int ks = 0; ks < 2; ks++)
#pragma unroll
                for (int np = 0; np < 2; np++) {
                    int row = ks * 16 + (q & 1) * 8 + rl;
                    int jj = part * 4 + np * 2 + (q >> 1);
                    uint32_t r4[4];
                    ldsm4t(r4, wb + row * 128 + (uint32_t)(((jj ^ (row & 7)) << 4)));
                    wf[part][ks][np * 2][0] = r4[0]; wf[part][ks][np * 2][1] = r4[1];
                    wf[part][ks][np * 2 + 1][0] = r4[2]; wf[part][ks][np * 2 + 1][1] = r4[3];
                }
#pragma unroll
        for (int mt = 0; mt < 2; mt++) {
            int rowa = warp * 32 + mt * 16 + (q & 1) * 8 + rl;
            uint32_t rb = xb + rowa * 128;
            uint32_t ah[2][4], al[2][4];
#pragma unroll
            for (int ks = 0; ks < 2; ks++) {
                int c0 = ks * 2 + (q >> 1);
                ldsm4(ah[ks], rb + (uint32_t)(((c0 ^ (rowa & 7)) << 4)));
            }
#pragma unroll
            for (int ks = 0; ks < 2; ks++) {
                int c0 = 4 + ks * 2 + (q >> 1);
                ldsm4(al[ks], rb + (uint32_t)(((c0 ^ (rowa & 7)) << 4)));
            }
#pragma unroll
            for (int nt = 0; nt < 4; nt++) {
                mma16816(acc[mt][nt], ah[0], wf[0][0][nt]);   // hi*hi k0-15
                mma16816(acc[mt][nt], ah[1], wf[0][1][nt]);   // hi*hi k16-31
                mma16816(acc[mt][nt], ah[0], wf[1][0][nt]);   // hi*lo
                mma16816(acc[mt][nt], ah[1], wf[1][1][nt]);
                mma16816(acc[mt][nt], al[0], wf[0][0][nt]);   // lo*hi
                mma16816(acc[mt][nt], al[1], wf[0][1][nt]);
            }
        }
    };

    // ---- prologue ----
    uint4 wtmp[2], wcur[2], wnew[2];
    WLDG(0, wtmp); WSTS(0, wtmp);      // buf0 = W(0); published by iter-0 barrier
    WLDG(1, wcur);                     // wcur = W(1)
    FETCH(0); FETCH(1); FETCH(2); FETCH(3);
    ISSUE(0); cp_commit();
    FETCH(4); ISSUE(1); cp_commit();
    FETCH(5); ISSUE(2); cp_commit();

#pragma unroll 4
    for (int t = 0; t < KT; t++) {
        if (t + 2 < KT) WLDG(t + 2, wnew);       // regs, full-iter latency slack
        if (t + 6 < KT) FETCH(t + 6);
        cp_wait<2>();            // tap t gathers landed (this thread)
        __syncthreads();         // stage data + W buf publications visible
        if (t + 1 < KT) WSTS((t + 1) & 1, wcur); // WAR-safe: readers of buf (t+1)&1 passed barrier
        COMPUTE(t);
        if (t + 3 < KT) ISSUE(t + 3);
        cp_commit();
        wcur[0] = wnew[0]; wcur[1] = wnew[1];
    }

    // ---- epilogue: bias + store + fused BN partials from fragments ----
    float2 bp[4];
#pragma unroll
    for (int nt = 0; nt < 4; nt++)
        bp[nt] = *(const float2*)(bconv + nt * 8 + 2 * tq);

    float s1[4][2], s2[4][2];
#pragma unroll
    for (int nt = 0; nt < 4; nt++) { s1[nt][0] = s1[nt][1] = s2[nt][0] = s2[nt][1] = 0.f; }

#pragma unroll
    for (int mt = 0; mt < 2; mt++) {
        int r0 = warp * 32 + mt * 16 + g;
        int r1 = r0 + 8;
        bool ok0 = (vb + r0) < n, ok1 = (vb + r1) < n;
#pragma unroll
        for (int nt = 0; nt < 4; nt++) {
            if (ok0) {
                float y0 = acc[mt][nt][0] + bp[nt].x;
                float y1 = acc[mt][nt][1] + bp[nt].y;
                *(float2*)(out + (size_t)(vb + r0) * C + nt * 8 + 2 * tq) = make_float2(y0, y1);
                s1[nt][0] += y0; s1[nt][1] += y1;
                s2[nt][0] += y0 * y0; s2[nt][1] += y1 * y1;
            }
            if (ok1) {
                float y0 = acc[mt][nt][2] + bp[nt].x;
                float y1 = acc[mt][nt][3] + bp[nt].y;
                *(float2*)(out + (size_t)(vb + r1) * C + nt * 8 + 2 * tq) = make_float2(y0, y1);
                s1[nt][0] += y0; s1[nt][1] += y1;
                s2[nt][0] += y0 * y0; s2[nt][1] += y1 * y1;
            }
        }
    }
#pragma unroll
    for (int nt = 0; nt < 4; nt++)
#pragma unroll
        for (int e = 0; e < 2; e++) {
#pragma unroll
            for (int msk = 4; msk < 32; msk <<= 1) {
                s1[nt][e] += __shfl_xor_sync(0xffffffffu, s1[nt][e], msk);
                s2[nt][e] += __shfl_xor_sync(0xffffffffu, s2[nt][e], msk);
            }
        }
    float* red = (float*)(smem + OFF_RED);
    if (lane < 4) {
#pragma unroll
        for (int nt = 0; nt < 4; nt++)
#pragma unroll
            for (int e = 0; e < 2; e++) {
                int col = nt * 8 + 2 * tq + e;
                red[warp * 64 + col] = s1[nt][e];
                red[warp * 64 + 32 + col] = s2[nt][e];
            }
    }
    __syncthreads();
    if (tid < C) {
        float a = 0.f, b = 0.f;
#pragma unroll
        for (int w = 0; w < 4; w++) { a += red[w * 64 + tid]; b += red[w * 64 + 32 + tid]; }
        g_part[blockIdx.x * 2 * C + tid] = a;
        g_part[blockIdx.x * 2 * C + C + tid] = b;
    }
}

// ---------------- fallback path ----------------
__global__ void transpose_w(const float* __restrict__ W, int total) {
    int i = blockIdx.x * blockDim.x + threadIdx.x;
    if (i < total) {
        int k = i / (C * C), r = i % (C * C);
        int cin = r / C, cout = r % C;
        g_Wt[k * C * C + cout * C + cin] = W[i];
    }
}

__global__ __launch_bounds__(256) void conv_generic(
    const float* __restrict__ x, const int* __restrict__ nbr,
    const float* __restrict__ bconv, float* __restrict__ out,
    int n, int kt)
{
    __shared__ __align__(16) float xsm[8][16][C];
    int warp = threadIdx.x >> 5, lane = threadIdx.x & 31;
    int v0 = blockIdx.x * 128 + warp * 16;
    float b = bconv[lane];
    float acc[16];
#pragma unroll
    for (int i = 0; i < 16; i++) acc[i] = b;
    for (int k = 0; k < kt; k++) {
        float4 w[8];
        const float4* wp = (const float4*)(g_Wt + k * C * C + lane * C);
#pragma unroll
        for (int j = 0; j < 8; j++) w[j] = wp[j];
        unsigned vm = 0;
#pragma unroll
        for (int i = 0; i < 16; i++) {
            int v = v0 + i;
            if (v < n) {
                int idx = __ldg(&nbr[(size_t)v * kt + k]);
                if (idx >= 0) { vm |= (1u << i); xsm[warp][i][lane] = x[(size_t)idx * C + lane]; }
            }
        }
        __syncwarp();
#pragma unroll
        for (int i = 0; i < 16; i++) {
            if ((vm >> i) & 1u) {
                const float4* xs = (const float4*)xsm[warp][i];
                float a = acc[i];
#pragma unroll
                for (int j = 0; j < 8; j++) {
                    float4 xv = xs[j];
                    a = fmaf(xv.x, w[j].x, a); a = fmaf(xv.y, w[j].y, a);
                    a = fmaf(xv.z, w[j].z, a); a = fmaf(xv.w, w[j].w, a);
                }
                acc[i] = a;
            }
        }
        __syncwarp();
    }
#pragma unroll
    for (int i = 0; i < 16; i++) {
        int v = v0 + i;
        if (v < n) out[(size_t)v * C + lane] = acc[i];
    }
}

__global__ __launch_bounds__(256) void bn_partial(const float* __restrict__ out, int n) {
    int lane = threadIdx.x & 31, w = threadIdx.x >> 5;
    float s = 0.f, s2 = 0.f;
    for (int r = blockIdx.x * 8 + w; r < n; r += gridDim.x * 8) {
        float v = out[(size_t)r * C + lane];
        s += v; s2 += v * v;
    }
    __shared__ float sh[2][8][C];
    sh[0][w][lane] = s; sh[1][w][lane] = s2;
    __syncthreads();
    if (threadIdx.x < C) {
        float S = 0.f, S2 = 0.f;
#pragma unroll
        for (int j = 0; j < 8; j++) { S += sh[0][j][threadIdx.x]; S2 += sh[1][j][threadIdx.x]; }
        g_part[blockIdx.x * 2 * C + threadIdx.x] = S;
        g_part[blockIdx.x * 2 * C + C + threadIdx.x] = S2;
    }
}

__global__ __launch_bounds__(256) void bn_mid(int nblocks) {
    int lane = threadIdx.x & 31, w = threadIdx.x >> 5;
    float S = 0.f, S2 = 0.f;
    for (int b = blockIdx.x + w * 64; b < nblocks; b += 512) {
        S  += g_part[b * 2 * C + lane];
        S2 += g_part[b * 2 * C + C + lane];
    }
    __shared__ float sh[2][8][C];
    sh[0][w][lane] = S; sh[1][w][lane] = S2;
    __syncthreads();
    if (threadIdx.x < C) {
        float a = 0.f, a2 = 0.f;
#pragma unroll
        for (int j = 0; j < 8; j++) { a += sh[0][j][threadIdx.x]; a2 += sh[1][j][threadIdx.x]; }
        g_part2[blockIdx.x * 2 * C + threadIdx.x] = a;
        g_part2[blockIdx.x * 2 * C + C + threadIdx.x] = a2;
    }
}

__global__ __launch_bounds__(256) void bn_final2(int n) {
    int lane = threadIdx.x & 31, w = threadIdx.x >> 5;
    float S = 0.f, S2 = 0.f;
    for (int b = w; b < 64; b += 8) {
        S  += g_part2[b * 2 * C + lane];
        S2 += g_part2[b * 2 * C + C + lane];
    }
    __shared__ float sh[2][8][C];
    sh[0][w][lane] = S; sh[1][w][lane] = S2;
    __syncthreads();
    if (threadIdx.x < C) {
        float a = 0.f, a2 = 0.f;
#pragma unroll
        for (int j = 0; j < 8; j++) { a += sh[0][j][threadIdx.x]; a2 += sh[1][j][threadIdx.x]; }
        float mean = a / (float)n;
        float var = a2 / (float)n - mean * mean;
        g_mean[threadIdx.x] = mean;
        g_rstd[threadIdx.x] = rsqrtf(var + EPSBN);
    }
}

__global__ __launch_bounds__(256) void apply_kernel(
    const float* __restrict__ gamma, const float* __restrict__ beta,
    const float* __restrict__ Wlin, const float* __restrict__ blin,
    float* __restrict__ out, int n)
{
    __shared__ __align__(16) float ysm[8][4][C];
    int lane = threadIdx.x & 31, w = threadIdx.x >> 5;
    float m = g_mean[lane], rs = g_rstd[lane];
    float ga = gamma[lane], be = beta[lane];
    F2U blu; blu.f = make_float2(blin[lane], 0.f);

    ull wl[16];
    const ull* wp = (const ull*)(Wlin + lane * C);
#pragma unroll
    for (int p = 0; p < 16; p++) wl[p] = wp[p];

    for (int v4 = (blockIdx.x * 8 + w) * 4; v4 < n; v4 += gridDim.x * 32) {
        float y[4];
#pragma unroll
        for (int qq = 0; qq < 4; qq++) {
            int v = v4 + qq;
            float o = (v < n) ? out[(size_t)v * C + lane] : 0.f;
            float t = fmaf((o - m) * rs, ga, be);
            y[qq] = (t > 0.f) ? t : expm1f(t);
            ysm[w][qq][lane] = y[qq];
        }
        __syncwarp();
#pragma unroll
        for (int qq = 0; qq < 4; qq++) {
            int v = v4 + qq;
            if (v < n) {
                const ull* ys = (const ull*)ysm[w][qq];
                ull z2 = blu.u;
#pragma unroll
                for (int p = 0; p < 16; p++) z2 = fma2(ys[p], wl[p], z2);
                F2U r; r.u = z2;
                out[(size_t)v * C + lane] = r.f.x + r.f.y;
            }
        }
        __syncwarp();
    }
}

extern "C" void kernel_launch(void* const* d_in, const int* in_sizes, int n_in,
                              void* d_out, int out_size)
{
    const float* x     = (const float*)d_in[0];
    const int*   nbr   = (const int*)d_in[1];
    const float* Wc    = (const float*)d_in[2];
    const float* bc    = (const float*)d_in[3];
    const float* gamma = (const float*)d_in[4];
    const float* beta  = (const float*)d_in[5];
    const float* Wl    = (const float*)d_in[6];
    const float* bl    = (const float*)d_in[7];
    float* out = (float*)d_out;

    int n  = in_sizes[0] / C;
    int kt = in_sizes[1] / n;
    int wtot = in_sizes[2];

    int nb = (n + MB - 1) / MB;
    if (kt == KTAP && n <= MAXN && nb <= MAXBLK) {
        static int smem_set = 0;
        if (!smem_set) {
            cudaFuncSetAttribute(conv_mma<KTAP>,
                                 cudaFuncAttributeMaxDynamicSharedMemorySize, SMEM_SZ);
            smem_set = 1;
        }
        convert_x<<<(n + 255) / 256, 256>>>(x, n);
        convert_w<<<(wtot + 255) / 256, 256>>>(Wc, wtot);
        conv_mma<KTAP><<<nb, CTHREADS, SMEM_SZ>>>(nbr, bc, out, n);
        bn_mid<<<64, 256>>>(nb);
        bn_final2<<<1, 256>>>(n);
    } else {
        transpose_w<<<(wtot + 255) / 256, 256>>>(Wc, wtot);
        conv_generic<<<(n + 127) / 128, 256>>>(x, nbr, bc, out, n, kt);
        bn_partial<<<512, 256>>>(out, n);
        bn_mid<<<64, 256>>>(512);
        bn_final2<<<1, 256>>>(n);
    }
    apply_kernel<<<2048, 256>>>(gamma, beta, Wl, bl, out, n);
}

// round 15
// speedup vs baseline: 1.1435x; 1.1435x over previous
#include <cuda_runtime.h>
#include <cuda_bf16.h>
#include <cstdint>

#define C 32
#define EPSBN 1e-5f
#define KTAP 125
#define MAXN 500000
#define MAXBLK 8192
#define NSTG 4
#define MB 128                 // voxels per block
#define CTHREADS 256           // 8 warps x 16 voxels (1 m-tile each)

typedef unsigned long long ull;

// smem layout (bytes)
#define OFF_X   0                       // 4 stages x 16384 (x tiles, swizzled 128B rows)
#define OFF_W   65536                   // 4 stages x 4096  (W tiles)
#define OFF_RED 81920                   // 8 warps x 64 floats = 2048
#define SMEM_SZ 84224

// ---- device scratch ----
__device__ __align__(16) unsigned char g_xhl[(size_t)MAXN * 128];  // [N][hi 64B | lo 64B]
__device__ __align__(16) unsigned char g_whl[KTAP * 4096];         // [K][cin][hi 64B | lo 64B]
__device__ __align__(16) float g_Wt[KTAP * C * C];                 // fallback
__device__ float g_part[MAXBLK * 2 * C];
__device__ float g_part2[64 * 2 * C];
__device__ float g_mean[C];
__device__ float g_rstd[C];

// ---- PTX helpers ----
__device__ __forceinline__ void cp_async16(uint32_t dst, const void* src) {
    asm volatile("cp.async.cg.shared.global [%0], [%1], 16;" :: "r"(dst), "l"(src));
}
__device__ __forceinline__ void cp_async16z(uint32_t dst, const void* src, uint32_t sz) {
    asm volatile("cp.async.cg.shared.global [%0], [%1], 16, %2;" :: "r"(dst), "l"(src), "r"(sz));
}
__device__ __forceinline__ void cp_commit() { asm volatile("cp.async.commit_group;"); }
template <int N_> __device__ __forceinline__ void cp_wait() {
    asm volatile("cp.async.wait_group %0;" :: "n"(N_));
}
__device__ __forceinline__ void ldsm4(uint32_t* r, uint32_t a) {
    asm volatile("ldmatrix.sync.aligned.m8n8.x4.shared.b16 {%0,%1,%2,%3}, [%4];"
                 : "=r"(r[0]), "=r"(r[1]), "=r"(r[2]), "=r"(r[3]) : "r"(a));
}
__device__ __forceinline__ void ldsm4t(uint32_t* r, uint32_t a) {
    asm volatile("ldmatrix.sync.aligned.m8n8.x4.trans.shared.b16 {%0,%1,%2,%3}, [%4];"
                 : "=r"(r[0]), "=r"(r[1]), "=r"(r[2]), "=r"(r[3]) : "r"(a));
}
__device__ __forceinline__ void mma16816(float* c, const uint32_t* a, const uint32_t* b) {
    asm volatile("mma.sync.aligned.m16n8k16.row.col.f32.bf16.bf16.f32 "
                 "{%0,%1,%2,%3}, {%4,%5,%6,%7}, {%8,%9}, {%0,%1,%2,%3};"
                 : "+f"(c[0]), "+f"(c[1]), "+f"(c[2]), "+f"(c[3])
                 : "r"(a[0]), "r"(a[1]), "r"(a[2]), "r"(a[3]), "r"(b[0]), "r"(b[1]));
}
__device__ __forceinline__ ull fma2(ull a, ull b, ull c) {
    ull d; asm("fma.rn.f32x2 %0, %1, %2, %3;" : "=l"(d) : "l"(a), "l"(b), "l"(c)); return d;
}
union F2U { float2 f; ull u; };

// ---------------- pre-convert x -> [hi|lo] bf16 rows ----------------
__global__ void convert_x(const float* __restrict__ x, int n) {
    int v = blockIdx.x * blockDim.x + threadIdx.x;
    if (v >= n) return;
    const float* xr = x + (size_t)v * C;
    __nv_bfloat16 hb[C], lb[C];
#pragma unroll
    for (int i = 0; i < C; i++) {
        float f = xr[i];
        __nv_bfloat16 h = __float2bfloat16(f);
        hb[i] = h;
        lb[i] = __float2bfloat16(f - __bfloat162float(h));
    }
    uint4* dst = (uint4*)(g_xhl + (size_t)v * 128);
    const uint4* hp = (const uint4*)hb;
    const uint4* lp = (const uint4*)lb;
#pragma unroll
    for (int q = 0; q < 4; q++) dst[q] = hp[q];
#pragma unroll
    for (int q = 0; q < 4; q++) dst[4 + q] = lp[q];
}

// ---------------- pre-convert W [K][CIN][COUT] -> [K][cin][hi|lo] ----------------
__global__ void convert_w(const float* __restrict__ W, int total) {
    int i = blockIdx.x * blockDim.x + threadIdx.x;
    if (i >= total) return;
    int k = i / (C * C), r = i % (C * C);
    int cin = r >> 5, cout = r & 31;
    float f = W[i];
    __nv_bfloat16 h = __float2bfloat16(f);
    __nv_bfloat16 l = __float2bfloat16(f - __bfloat162float(h));
    __nv_bfloat16* row = (__nv_bfloat16*)(g_whl + (size_t)k * 4096 + cin * 128);
    row[cout] = h;
    row[32 + cout] = l;
}

// ---------------- mma sparse conv (8 warps, 1 m-tile each) ----------------
template <int KT>
__global__ __launch_bounds__(CTHREADS, 2) void conv_mma(
    const int* __restrict__ nbr, const float* __restrict__ bconv,
    float* __restrict__ out, int n)
{
    extern __shared__ __align__(16) unsigned char smem[];
    const uint32_t sb = (uint32_t)__cvta_generic_to_shared(smem);
    const int tid = threadIdx.x, warp = tid >> 5, lane = tid & 31;
    const int vb = blockIdx.x * MB;
    const int myrow = tid >> 1;            // gather row 0..127 (2 threads per row)
    const int half = tid & 1;              // this thread's 4-chunk half
    const int vg = vb + myrow;
    const bool vok = vg < n;
    const int q = lane >> 3, rl = lane & 7;   // ldmatrix addressing
    const int g = lane >> 2, tq = lane & 3;   // mma fragment coords
    const int* nrow = nbr + (size_t)(vok ? vg : 0) * KT;

    float acc[4][4];
#pragma unroll
    for (int b = 0; b < 4; b++)
#pragma unroll
        for (int c = 0; c < 4; c++) acc[b][c] = 0.f;

    int nidx[NSTG];

    auto FETCH = [&](int tt) {
        nidx[tt & 3] = vok ? __ldg(nrow + tt) : -1;
    };
    auto ISSUE = [&](int tt) {
        int s = tt & 3;
        int id = nidx[s];
        uint32_t sz = (id >= 0) ? 16u : 0u;
        const unsigned char* src = g_xhl + (size_t)(id < 0 ? 0 : id) * 128;
        uint32_t xdst = sb + OFF_X + s * 16384 + myrow * 128;
#pragma unroll
        for (int j = 0; j < 4; j++) {
            int jj = half * 4 + j;
            cp_async16z(xdst + (uint32_t)(((jj ^ (myrow & 7)) << 4)), src + jj * 16, sz);
        }
        // W tile 4KB: 256 threads x 1 chunk, swizzled 128B rows
        {
            int cc = tid;
            int row = cc >> 3, jj = cc & 7;
            cp_async16(sb + OFF_W + s * 4096 + row * 128 + (uint32_t)(((jj ^ (row & 7)) << 4)),
                       g_whl + (size_t)tt * 4096 + cc * 16);
        }
    };
    auto COMPUTE = [&](int tt) {
        int s = tt & 3;
        uint32_t xb = sb + OFF_X + s * 16384;
        uint32_t wb = sb + OFF_W + s * 4096;
        // W fragments: wf[part][kstep][ntile][2]
        uint32_t wf[2][2][4][2];
#pragma unroll
        for (int part = 0; part < 2; part++)
#pragma unroll
            for (int ks = 0; ks < 2; ks++)
#pragma unroll
                for (int np = 0; np < 2; np++) {
                    int row = ks * 16 + (q & 1) * 8 + rl;
                    int jj = part * 4 + np * 2 + (q >> 1);
                    uint32_t r4[4];
                    ldsm4t(r4, wb + row * 128 + (uint32_t)(((jj ^ (row & 7)) << 4)));
                    wf[part][ks][np * 2][0] = r4[0]; wf[part][ks][np * 2][1] = r4[1];
                    wf[part][ks][np * 2 + 1][0] = r4[2]; wf[part][ks][np * 2 + 1][1] = r4[3];
                }
        int rowa = warp * 16 + (q & 1) * 8 + rl;
        uint32_t rb = xb + rowa * 128;
        uint32_t ah[2][4], al[2][4];
#pragma unroll
        for (int ks = 0; ks < 2; ks++) {
            int c0 = ks * 2 + (q >> 1);
            ldsm4(ah[ks], rb + (uint32_t)(((c0 ^ (rowa & 7)) << 4)));
        }
#pragma unroll
        for (int ks = 0; ks < 2; ks++) {
            int c0 = 4 + ks * 2 + (q >> 1);
            ldsm4(al[ks], rb + (uint32_t)(((c0 ^ (rowa & 7)) << 4)));
        }
#pragma unroll
        for (int nt = 0; nt < 4; nt++) {
            mma16816(acc[nt], ah[0], wf[0][0][nt]);   // hi*hi k0-15
            mma16816(acc[nt], ah[1], wf[0][1][nt]);   // hi*hi k16-31
            mma16816(acc[nt], ah[0], wf[1][0][nt]);   // hi*lo
            mma16816(acc[nt], ah[1], wf[1][1][nt]);
            mma16816(acc[nt], al[0], wf[0][0][nt]);   // lo*hi
            mma16816(acc[nt], al[1], wf[0][1][nt]);
        }
    };

    // prologue: interleaved so FETCH(t+4) never clobbers a slot before ISSUE(t) reads it
    FETCH(0); FETCH(1); FETCH(2); FETCH(3);
    ISSUE(0); cp_commit();
    FETCH(4); ISSUE(1); cp_commit();
    FETCH(5); ISSUE(2); cp_commit();

#pragma unroll 4
    for (int t = 0; t < KT; t++) {
        if (t + 6 < KT) FETCH(t + 6);
        cp_wait<2>();            // tap t gathers + weights landed (this thread)
        __syncthreads();         // everyone's staged data visible
        COMPUTE(t);
        if (t + 3 < KT) ISSUE(t + 3);   // writes stage (t-1)&3: all readers passed barrier
        cp_commit();
    }

    // ---- epilogue: bias + store + fused BN partials from fragments ----
    float2 bp[4];
#pragma unroll
    for (int nt = 0; nt < 4; nt++)
        bp[nt] = *(const float2*)(bconv + nt * 8 + 2 * tq);

    float s1[4][2], s2[4][2];
#pragma unroll
    for (int nt = 0; nt < 4; nt++) { s1[nt][0] = s1[nt][1] = s2[nt][0] = s2[nt][1] = 0.f; }

    {
        int r0 = warp * 16 + g;
        int r1 = r0 + 8;
        bool ok0 = (vb + r0) < n, ok1 = (vb + r1) < n;
#pragma unroll
        for (int nt = 0; nt < 4; nt++) {
            if (ok0) {
                float y0 = acc[nt][0] + bp[nt].x;
                float y1 = acc[nt][1] + bp[nt].y;
                *(float2*)(out + (size_t)(vb + r0) * C + nt * 8 + 2 * tq) = make_float2(y0, y1);
                s1[nt][0] += y0; s1[nt][1] += y1;
                s2[nt][0] += y0 * y0; s2[nt][1] += y1 * y1;
            }
            if (ok1) {
                float y0 = acc[nt][2] + bp[nt].x;
                float y1 = acc[nt][3] + bp[nt].y;
                *(float2*)(out + (size_t)(vb + r1) * C + nt * 8 + 2 * tq) = make_float2(y0, y1);
                s1[nt][0] += y0; s1[nt][1] += y1;
                s2[nt][0] += y0 * y0; s2[nt][1] += y1 * y1;
            }
        }
    }
    // reduce across lanes sharing the same tq (stride 4, 8, 16)
#pragma unroll
    for (int nt = 0; nt < 4; nt++)
#pragma unroll
        for (int e = 0; e < 2; e++) {
#pragma unroll
            for (int msk = 4; msk < 32; msk <<= 1) {
                s1[nt][e] += __shfl_xor_sync(0xffffffffu, s1[nt][e], msk);
                s2[nt][e] += __shfl_xor_sync(0xffffffffu, s2[nt][e], msk);
            }
        }
    float* red = (float*)(smem + OFF_RED);
    if (lane < 4) {
#pragma unroll
        for (int nt = 0; nt < 4; nt++)
#pragma unroll
            for (int e = 0; e < 2; e++) {
                int col = nt * 8 + 2 * tq + e;
                red[warp * 64 + col] = s1[nt][e];
                red[warp * 64 + 32 + col] = s2[nt][e];
            }
    }
    __syncthreads();
    if (tid < C) {
        float a = 0.f, b = 0.f;
#pragma unroll
        for (int w = 0; w < 8; w++) { a += red[w * 64 + tid]; b += red[w * 64 + 32 + tid]; }
        g_part[blockIdx.x * 2 * C + tid] = a;
        g_part[blockIdx.x * 2 * C + C + tid] = b;
    }
}

// ---------------- fallback path ----------------
__global__ void transpose_w(const float* __restrict__ W, int total) {
    int i = blockIdx.x * blockDim.x + threadIdx.x;
    if (i < total) {
        int k = i / (C * C), r = i % (C * C);
        int cin = r / C, cout = r % C;
        g_Wt[k * C * C + cout * C + cin] = W[i];
    }
}

__global__ __launch_bounds__(256) void conv_generic(
    const float* __restrict__ x, const int* __restrict__ nbr,
    const float* __restrict__ bconv, float* __restrict__ out,
    int n, int kt)
{
    __shared__ __align__(16) float xsm[8][16][C];
    int warp = threadIdx.x >> 5, lane = threadIdx.x & 31;
    int v0 = blockIdx.x * 128 + warp * 16;
    float b = bconv[lane];
    float acc[16];
#pragma unroll
    for (int i = 0; i < 16; i++) acc[i] = b;
    for (int k = 0; k < kt; k++) {
        float4 w[8];
        const float4* wp = (const float4*)(g_Wt + k * C * C + lane * C);
#pragma unroll
        for (int j = 0; j < 8; j++) w[j] = wp[j];
        unsigned vm = 0;
#pragma unroll
        for (int i = 0; i < 16; i++) {
            int v = v0 + i;
            if (v < n) {
                int idx = __ldg(&nbr[(size_t)v * kt + k]);
                if (idx >= 0) { vm |= (1u << i); xsm[warp][i][lane] = x[(size_t)idx * C + lane]; }
            }
        }
        __syncwarp();
#pragma unroll
        for (int i = 0; i < 16; i++) {
            if ((vm >> i) & 1u) {
                const float4* xs = (const float4*)xsm[warp][i];
                float a = acc[i];
#pragma unroll
                for (int j = 0; j < 8; j++) {
                    float4 xv = xs[j];
                    a = fmaf(xv.x, w[j].x, a); a = fmaf(xv.y, w[j].y, a);
                    a = fmaf(xv.z, w[j].z, a); a = fmaf(xv.w, w[j].w, a);
                }
                acc[i] = a;
            }
        }
        __syncwarp();
    }
#pragma unroll
    for (int i = 0; i < 16; i++) {
        int v = v0 + i;
        if (v < n) out[(size_t)v * C + lane] = acc[i];
    }
}

__global__ __launch_bounds__(256) void bn_partial(const float* __restrict__ out, int n) {
    int lane = threadIdx.x & 31, w = threadIdx.x >> 5;
    float s = 0.f, s2 = 0.f;
    for (int r = blockIdx.x * 8 + w; r < n; r += gridDim.x * 8) {
        float v = out[(size_t)r * C + lane];
        s += v; s2 += v * v;
    }
    __shared__ float sh[2][8][C];
    sh[0][w][lane] = s; sh[1][w][lane] = s2;
    __syncthreads();
    if (threadIdx.x < C) {
        float S = 0.f, S2 = 0.f;
#pragma unroll
        for (int j = 0; j < 8; j++) { S += sh[0][j][threadIdx.x]; S2 += sh[1][j][threadIdx.x]; }
        g_part[blockIdx.x * 2 * C + threadIdx.x] = S;
        g_part[blockIdx.x * 2 * C + C + threadIdx.x] = S2;
    }
}

__global__ __launch_bounds__(256) void bn_mid(int nblocks) {
    int lane = threadIdx.x & 31, w = threadIdx.x >> 5;
    float S = 0.f, S2 = 0.f;
    for (int b = blockIdx.x + w * 64; b < nblocks; b += 512) {
        S  += g_part[b * 2 * C + lane];
        S2 += g_part[b * 2 * C + C + lane];
    }
    __shared__ float sh[2][8][C];
    sh[0][w][lane] = S; sh[1][w][lane] = S2;
    __syncthreads();
    if (threadIdx.x < C) {
        float a = 0.f, a2 = 0.f;
#pragma unroll
        for (int j = 0; j < 8; j++) { a += sh[0][j][threadIdx.x]; a2 += sh[1][j][threadIdx.x]; }
        g_part2[blockIdx.x * 2 * C + threadIdx.x] = a;
        g_part2[blockIdx.x * 2 * C + C + threadIdx.x] = a2;
    }
}

__global__ __launch_bounds__(256) void bn_final2(int n) {
    int lane = threadIdx.x & 31, w = threadIdx.x >> 5;
    float S = 0.f, S2 = 0.f;
    for (int b = w; b < 64; b += 8) {
        S  += g_part2[b * 2 * C + lane];
        S2 += g_part2[b * 2 * C + C + lane];
    }
    __shared__ float sh[2][8][C];
    sh[0][w][lane] = S; sh[1][w][lane] = S2;
    __syncthreads();
    if (threadIdx.x < C) {
        float a = 0.f, a2 = 0.f;
#pragma unroll
        for (int j = 0; j < 8; j++) { a += sh[0][j][threadIdx.x]; a2 += sh[1][j][threadIdx.x]; }
        float mean = a / (float)n;
        float var = a2 / (float)n - mean * mean;
        g_mean[threadIdx.x] = mean;
        g_rstd[threadIdx.x] = rsqrtf(var + EPSBN);
    }
}

__global__ __launch_bounds__(256) void apply_kernel(
    const float* __restrict__ gamma, const float* __restrict__ beta,
    const float* __restrict__ Wlin, const float* __restrict__ blin,
    float* __restrict__ out, int n)
{
    __shared__ __align__(16) float ysm[8][4][C];
    int lane = threadIdx.x & 31, w = threadIdx.x >> 5;
    float m = g_mean[lane], rs = g_rstd[lane];
    float ga = gamma[lane], be = beta[lane];
    F2U blu; blu.f = make_float2(blin[lane], 0.f);

    ull wl[16];
    const ull* wp = (const ull*)(Wlin + lane * C);
#pragma unroll
    for (int p = 0; p < 16; p++) wl[p] = wp[p];

    for (int v4 = (blockIdx.x * 8 + w) * 4; v4 < n; v4 += gridDim.x * 32) {
        float y[4];
#pragma unroll
        for (int qq = 0; qq < 4; qq++) {
            int v = v4 + qq;
            float o = (v < n) ? out[(size_t)v * C + lane] : 0.f;
            float t = fmaf((o - m) * rs, ga, be);
            y[qq] = (t > 0.f) ? t : expm1f(t);
            ysm[w][qq][lane] = y[qq];
        }
        __syncwarp();
#pragma unroll
        for (int qq = 0; qq < 4; qq++) {
            int v = v4 + qq;
            if (v < n) {
                const ull* ys = (const ull*)ysm[w][qq];
                ull z2 = blu.u;
#pragma unroll
                for (int p = 0; p < 16; p++) z2 = fma2(ys[p], wl[p], z2);
                F2U r; r.u = z2;
                out[(size_t)v * C + lane] = r.f.x + r.f.y;
            }
        }
        __syncwarp();
    }
}

extern "C" void kernel_launch(void* const* d_in, const int* in_sizes, int n_in,
                              void* d_out, int out_size)
{
    const float* x     = (const float*)d_in[0];
    const int*   nbr   = (const int*)d_in[1];
    const float* Wc    = (const float*)d_in[2];
    const float* bc    = (const float*)d_in[3];
    const float* gamma = (const float*)d_in[4];
    const float* beta  = (const float*)d_in[5];
    const float* Wl    = (const float*)d_in[6];
    const float* bl    = (const float*)d_in[7];
    float* out = (float*)d_out;

    int n  = in_sizes[0] / C;
    int kt = in_sizes[1] / n;
    int wtot = in_sizes[2];

    int nb = (n + MB - 1) / MB;
    if (kt == KTAP && n <= MAXN && nb <= MAXBLK) {
        static int smem_set = 0;
        if (!smem_set) {
            cudaFuncSetAttribute(conv_mma<KTAP>,
                                 cudaFuncAttributeMaxDynamicSharedMemorySize, SMEM_SZ);
            smem_set = 1;
        }
        convert_x<<<(n + 255) / 256, 256>>>(x, n);
        convert_w<<<(wtot + 255) / 256, 256>>>(Wc, wtot);
        conv_mma<KTAP><<<nb, CTHREADS, SMEM_SZ>>>(nbr, bc, out, n);
        bn_mid<<<64, 256>>>(nb);
        bn_final2<<<1, 256>>>(n);
    } else {
        transpose_w<<<(wtot + 255) / 256, 256>>>(Wc, wtot);
        conv_generic<<<(n + 127) / 128, 256>>>(x, nbr, bc, out, n, kt);
        bn_partial<<<512, 256>>>(out, n);
        bn_mid<<<64, 256>>>(512);
        bn_final2<<<1, 256>>>(n);
    }
    apply_kernel<<<2048, 256>>>(gamma, beta, Wl, bl, out, n);
}

// round 16
// speedup vs baseline: 1.2778x; 1.1175x over previous
#include <cuda_runtime.h>
#include <cuda_bf16.h>
#include <cstdint>

#define C 32
#define EPSBN 1e-5f
#define KTAP 125
#define MAXN 500000
#define MAXBLK 8192
#define NSTG 4
#define MB 128                 // voxels per block
#define CTHREADS 128           // 4 warps x 32 voxels

typedef unsigned long long ull;

// smem layout (bytes)
#define OFF_X   0                       // 4 stages x 16384 (x tiles, swizzled 128B rows)
#define OFF_W   65536                   // 4 stages x 4096  (W tiles)
#define OFF_RED 81920                   // 4 warps x 64 floats
#define SMEM_SZ 83200

// ---- device scratch ----
__device__ __align__(16) unsigned char g_xhl[(size_t)MAXN * 128];  // [N][hi 64B | lo 64B]
__device__ __align__(16) unsigned char g_whl[KTAP * 4096];         // [K][cin][hi 64B | lo 64B]
__device__ __align__(16) float g_Wt[KTAP * C * C];                 // fallback
__device__ float g_part[MAXBLK * 2 * C];
__device__ float g_part2[64 * 2 * C];
__device__ float g_mean[C];
__device__ float g_rstd[C];

// ---- PTX helpers ----
__device__ __forceinline__ void cp_async16(uint32_t dst, const void* src) {
    asm volatile("cp.async.cg.shared.global [%0], [%1], 16;" :: "r"(dst), "l"(src));
}
__device__ __forceinline__ void cp_async16z(uint32_t dst, const void* src, uint32_t sz) {
    asm volatile("cp.async.cg.shared.global [%0], [%1], 16, %2;" :: "r"(dst), "l"(src), "r"(sz));
}
__device__ __forceinline__ void cp_commit() { asm volatile("cp.async.commit_group;"); }
template <int N_> __device__ __forceinline__ void cp_wait() {
    asm volatile("cp.async.wait_group %0;" :: "n"(N_));
}
__device__ __forceinline__ void ldsm4(uint32_t* r, uint32_t a) {
    asm volatile("ldmatrix.sync.aligned.m8n8.x4.shared.b16 {%0,%1,%2,%3}, [%4];"
                 : "=r"(r[0]), "=r"(r[1]), "=r"(r[2]), "=r"(r[3]) : "r"(a));
}
__device__ __forceinline__ void ldsm4t(uint32_t* r, uint32_t a) {
    asm volatile("ldmatrix.sync.aligned.m8n8.x4.trans.shared.b16 {%0,%1,%2,%3}, [%4];"
                 : "=r"(r[0]), "=r"(r[1]), "=r"(r[2]), "=r"(r[3]) : "r"(a));
}
__device__ __forceinline__ void mma16816(float* c, const uint32_t* a, const uint32_t* b) {
    asm volatile("mma.sync.aligned.m16n8k16.row.col.f32.bf16.bf16.f32 "
                 "{%0,%1,%2,%3}, {%4,%5,%6,%7}, {%8,%9}, {%0,%1,%2,%3};"
                 : "+f"(c[0]), "+f"(c[1]), "+f"(c[2]), "+f"(c[3])
                 : "r"(a[0]), "r"(a[1]), "r"(a[2]), "r"(a[3]), "r"(b[0]), "r"(b[1]));
}
__device__ __forceinline__ ull fma2(ull a, ull b, ull c) {
    ull d; asm("fma.rn.f32x2 %0, %1, %2, %3;" : "=l"(d) : "l"(a), "l"(b), "l"(c)); return d;
}
union F2U { float2 f; ull u; };
union BF2U { __nv_bfloat162 b; uint32_t u; };

// ---------------- pre-convert x -> [hi|lo] bf16 rows (warp-cooperative, coalesced) ----------------
__global__ void convert_x(const float* __restrict__ x, int n) {
    int wg = (blockIdx.x * blockDim.x + threadIdx.x) >> 5;  // warp handles 8 rows
    int lane = threadIdx.x & 31;
    int r0 = wg * 8;
    if (r0 >= n) return;
    const float4* src = (const float4*)(x + (size_t)r0 * C);
#pragma unroll
    for (int h = 0; h < 2; h++) {
        int f = lane + h * 32;               // float4 index within the 8-row group
        int row = r0 + (f >> 3), quad = f & 7;
        if (row < n) {
            float4 v = __ldg(src + f);
            __nv_bfloat16 h0 = __float2bfloat16(v.x), h1 = __float2bfloat16(v.y);
            __nv_bfloat16 h2 = __float2bfloat16(v.z), h3 = __float2bfloat16(v.w);
            BF2U hi0, hi1, lo0, lo1;
            hi0.b.x = h0; hi0.b.y = h1;
            hi1.b.x = h2; hi1.b.y = h3;
            lo0.b.x = __float2bfloat16(v.x - __bfloat162float(h0));
            lo0.b.y = __float2bfloat16(v.y - __bfloat162float(h1));
            lo1.b.x = __float2bfloat16(v.z - __bfloat162float(h2));
            lo1.b.y = __float2bfloat16(v.w - __bfloat162float(h3));
            unsigned char* dstrow = g_xhl + (size_t)row * 128;
            *(uint2*)(dstrow + quad * 8)      = make_uint2(hi0.u, hi1.u);
            *(uint2*)(dstrow + 64 + quad * 8) = make_uint2(lo0.u, lo1.u);
        }
    }
}

// ---------------- pre-convert W [K][CIN][COUT] -> [K][cin][hi|lo] ----------------
__global__ void convert_w(const float* __restrict__ W, int total) {
    int i = blockIdx.x * blockDim.x + threadIdx.x;
    if (i >= total) return;
    int k = i / (C * C), r = i % (C * C);
    int cin = r >> 5, cout = r & 31;
    float f = W[i];
    __nv_bfloat16 h = __float2bfloat16(f);
    __nv_bfloat16 l = __float2bfloat16(f - __bfloat162float(h));
    __nv_bfloat16* row = (__nv_bfloat16*)(g_whl + (size_t)k * 4096 + cin * 128);
    row[cout] = h;
    row[32 + cout] = l;
}

// ---------------- mma sparse conv (R13 champion, unchanged) ----------------
template <int KT>
__global__ __launch_bounds__(CTHREADS, 2) void conv_mma(
    const int* __restrict__ nbr, const float* __restrict__ bconv,
    float* __restrict__ out, int n)
{
    extern __shared__ __align__(16) unsigned char smem[];
    const uint32_t sb = (uint32_t)__cvta_generic_to_shared(smem);
    const int tid = threadIdx.x, warp = tid >> 5, lane = tid & 31;
    const int vb = blockIdx.x * MB;
    const int vg = vb + tid;
    const bool vok = vg < n;
    const int q = lane >> 3, rl = lane & 7;
    const int g = lane >> 2, tq = lane & 3;
    const int* nrow = nbr + (size_t)(vok ? vg : 0) * KT;

    float acc[2][4][4];
#pragma unroll
    for (int a = 0; a < 2; a++)
#pragma unroll
        for (int b = 0; b < 4; b++)
#pragma unroll
            for (int c = 0; c < 4; c++) acc[a][b][c] = 0.f;

    int nidx[NSTG];

    auto FETCH = [&](int tt) {
        nidx[tt & 3] = vok ? __ldg(nrow + tt) : -1;
    };
    auto ISSUE = [&](int tt) {
        int s = tt & 3;
        int id = nidx[s];
        uint32_t sz = (id >= 0) ? 16u : 0u;
        const unsigned char* src = g_xhl + (size_t)(id < 0 ? 0 : id) * 128;
        uint32_t xdst = sb + OFF_X + s * 16384 + tid * 128;
#pragma unroll
        for (int j = 0; j < 8; j++)
            cp_async16z(xdst + (uint32_t)(((j ^ (lane & 7)) << 4)), src + j * 16, sz);
#pragma unroll
        for (int h = 0; h < 2; h++) {
            int cc = tid + h * 128;
            int row = cc >> 3, jj = cc & 7;
            cp_async16(sb + OFF_W + s * 4096 + row * 128 + (uint32_t)(((jj ^ (row & 7)) << 4)),
                       g_whl + (size_t)tt * 4096 + cc * 16);
        }
    };
    auto COMPUTE = [&](int tt) {
        int s = tt & 3;
        uint32_t xb = sb + OFF_X + s * 16384;
        uint32_t wb = sb + OFF_W + s * 4096;
        uint32_t wf[2][2][4][2];
#pragma unroll
        for (int part = 0; part < 2; part++)
#pragma unroll
            for (int ks = 0; ks < 2; ks++)
#pragma unroll
                for (int np = 0; np < 2; np++) {
                    int row = ks * 16 + (q & 1) * 8 + rl;
                    int jj = part * 4 + np * 2 + (q >> 1);
                    uint32_t r4[4];
                    ldsm4t(r4, wb + row * 128 + (uint32_t)(((jj ^ (row & 7)) << 4)));
                    wf[part][ks][np * 2][0] = r4[0]; wf[part][ks][np * 2][1] = r4[1];
                    wf[part][ks][np * 2 + 1][0] = r4[2]; wf[part][ks][np * 2 + 1][1] = r4[3];
                }
#pragma unroll
        for (int mt = 0; mt < 2; mt++) {
            int rowa = warp * 32 + mt * 16 + (q & 1) * 8 + rl;
            uint32_t rb = xb + rowa * 128;
            uint32_t ah[2][4], al[2][4];
#pragma unroll
            for (int ks = 0; ks < 2; ks++) {
                int c0 = ks * 2 + (q >> 1);
                ldsm4(ah[ks], rb + (uint32_t)(((c0 ^ (rowa & 7)) << 4)));
            }
#pragma unroll
            for (int ks = 0; ks < 2; ks++) {
                int c0 = 4 + ks * 2 + (q >> 1);
                ldsm4(al[ks], rb + (uint32_t)(((c0 ^ (rowa & 7)) << 4)));
            }
#pragma unroll
            for (int nt = 0; nt < 4; nt++) {
                mma16816(acc[mt][nt], ah[0], wf[0][0][nt]);   // hi*hi k0-15
                mma16816(acc[mt][nt], ah[1], wf[0][1][nt]);   // hi*hi k16-31
                mma16816(acc[mt][nt], ah[0], wf[1][0][nt]);   // hi*lo
                mma16816(acc[mt][nt], ah[1], wf[1][1][nt]);
                mma16816(acc[mt][nt], al[0], wf[0][0][nt]);   // lo*hi
                mma16816(acc[mt][nt], al[1], wf[0][1][nt]);
            }
        }
    };

    // prologue: interleaved so FETCH(t+4) never clobbers a slot before ISSUE(t) reads it
    FETCH(0); FETCH(1); FETCH(2); FETCH(3);
    ISSUE(0); cp_commit();
    FETCH(4); ISSUE(1); cp_commit();
    FETCH(5); ISSUE(2); cp_commit();

#pragma unroll 4
    for (int t = 0; t < KT; t++) {
        if (t + 6 < KT) FETCH(t + 6);
        cp_wait<2>();
        __syncthreads();
        COMPUTE(t);
        if (t + 3 < KT) ISSUE(t + 3);
        cp_commit();
    }

    // ---- epilogue: bias + store + fused BN partials from fragments ----
    float2 bp[4];
#pragma unroll
    for (int nt = 0; nt < 4; nt++)
        bp[nt] = *(const float2*)(bconv + nt * 8 + 2 * tq);

    float s1[4][2], s2[4][2];
#pragma unroll
    for (int nt = 0; nt < 4; nt++) { s1[nt][0] = s1[nt][1] = s2[nt][0] = s2[nt][1] = 0.f; }

#pragma unroll
    for (int mt = 0; mt < 2; mt++) {
        int r0 = warp * 32 + mt * 16 + g;
        int r1 = r0 + 8;
        bool ok0 = (vb + r0) < n, ok1 = (vb + r1) < n;
#pragma unroll
        for (int nt = 0; nt < 4; nt++) {
            if (ok0) {
                float y0 = acc[mt][nt][0] + bp[nt].x;
                float y1 = acc[mt][nt][1] + bp[nt].y;
                *(float2*)(out + (size_t)(vb + r0) * C + nt * 8 + 2 * tq) = make_float2(y0, y1);
                s1[nt][0] += y0; s1[nt][1] += y1;
                s2[nt][0] += y0 * y0; s2[nt][1] += y1 * y1;
            }
            if (ok1) {
                float y0 = acc[mt][nt][2] + bp[nt].x;
                float y1 = acc[mt][nt][3] + bp[nt].y;
                *(float2*)(out + (size_t)(vb + r1) * C + nt * 8 + 2 * tq) = make_float2(y0, y1);
                s1[nt][0] += y0; s1[nt][1] += y1;
                s2[nt][0] += y0 * y0; s2[nt][1] += y1 * y1;
            }
        }
    }
#pragma unroll
    for (int nt = 0; nt < 4; nt++)
#pragma unroll
        for (int e = 0; e < 2; e++) {
#pragma unroll
            for (int msk = 4; msk < 32; msk <<= 1) {
                s1[nt][e] += __shfl_xor_sync(0xffffffffu, s1[nt][e], msk);
                s2[nt][e] += __shfl_xor_sync(0xffffffffu, s2[nt][e], msk);
            }
        }
    float* red = (float*)(smem + OFF_RED);
    if (lane < 4) {
#pragma unroll
        for (int nt = 0; nt < 4; nt++)
#pragma unroll
            for (int e = 0; e < 2; e++) {
                int col = nt * 8 + 2 * tq + e;
                red[warp * 64 + col] = s1[nt][e];
                red[warp * 64 + 32 + col] = s2[nt][e];
            }
    }
    __syncthreads();
    if (tid < C) {
        float a = 0.f, b = 0.f;
#pragma unroll
        for (int w = 0; w < 4; w++) { a += red[w * 64 + tid]; b += red[w * 64 + 32 + tid]; }
        g_part[blockIdx.x * 2 * C + tid] = a;
        g_part[blockIdx.x * 2 * C + C + tid] = b;
    }
}

// ---------------- fallback path ----------------
__global__ void transpose_w(const float* __restrict__ W, int total) {
    int i = blockIdx.x * blockDim.x + threadIdx.x;
    if (i < total) {
        int k = i / (C * C), r = i % (C * C);
        int cin = r / C, cout = r % C;
        g_Wt[k * C * C + cout * C + cin] = W[i];
    }
}

__global__ __launch_bounds__(256) void conv_generic(
    const float* __restrict__ x, const int* __restrict__ nbr,
    const float* __restrict__ bconv, float* __restrict__ out,
    int n, int kt)
{
    __shared__ __align__(16) float xsm[8][16][C];
    int warp = threadIdx.x >> 5, lane = threadIdx.x & 31;
    int v0 = blockIdx.x * 128 + warp * 16;
    float b = bconv[lane];
    float acc[16];
#pragma unroll
    for (int i = 0; i < 16; i++) acc[i] = b;
    for (int k = 0; k < kt; k++) {
        float4 w[8];
        const float4* wp = (const float4*)(g_Wt + k * C * C + lane * C);
#pragma unroll
        for (int j = 0; j < 8; j++) w[j] = wp[j];
        unsigned vm = 0;
#pragma unroll
        for (int i = 0; i < 16; i++) {
            int v = v0 + i;
            if (v < n) {
                int idx = __ldg(&nbr[(size_t)v * kt + k]);
                if (idx >= 0) { vm |= (1u << i); xsm[warp][i][lane] = x[(size_t)idx * C + lane]; }
            }
        }
        __syncwarp();
#pragma unroll
        for (int i = 0; i < 16; i++) {
            if ((vm >> i) & 1u) {
                const float4* xs = (const float4*)xsm[warp][i];
                float a = acc[i];
#pragma unroll
                for (int j = 0; j < 8; j++) {
                    float4 xv = xs[j];
                    a = fmaf(xv.x, w[j].x, a); a = fmaf(xv.y, w[j].y, a);
                    a = fmaf(xv.z, w[j].z, a); a = fmaf(xv.w, w[j].w, a);
                }
                acc[i] = a;
            }
        }
        __syncwarp();
    }
#pragma unroll
    for (int i = 0; i < 16; i++) {
        int v = v0 + i;
        if (v < n) out[(size_t)v * C + lane] = acc[i];
    }
}

__global__ __launch_bounds__(256) void bn_partial(const float* __restrict__ out, int n) {
    int lane = threadIdx.x & 31, w = threadIdx.x >> 5;
    float s = 0.f, s2 = 0.f;
    for (int r = blockIdx.x * 8 + w; r < n; r += gridDim.x * 8) {
        float v = out[(size_t)r * C + lane];
        s += v; s2 += v * v;
    }
    __shared__ float sh[2][8][C];
    sh[0][w][lane] = s; sh[1][w][lane] = s2;
    __syncthreads();
    if (threadIdx.x < C) {
        float S = 0.f, S2 = 0.f;
#pragma unroll
        for (int j = 0; j < 8; j++) { S += sh[0][j][threadIdx.x]; S2 += sh[1][j][threadIdx.x]; }
        g_part[blockIdx.x * 2 * C + threadIdx.x] = S;
        g_part[blockIdx.x * 2 * C + C + threadIdx.x] = S2;
    }
}

__global__ __launch_bounds__(256) void bn_mid(int nblocks) {
    int lane = threadIdx.x & 31, w = threadIdx.x >> 5;
    float S = 0.f, S2 = 0.f;
    for (int b = blockIdx.x + w * 64; b < nblocks; b += 512) {
        S  += g_part[b * 2 * C + lane];
        S2 += g_part[b * 2 * C + C + lane];
    }
    __shared__ float sh[2][8][C];
    sh[0][w][lane] = S; sh[1][w][lane] = S2;
    __syncthreads();
    if (threadIdx.x < C) {
        float a = 0.f, a2 = 0.f;
#pragma unroll
        for (int j = 0; j < 8; j++) { a += sh[0][j][threadIdx.x]; a2 += sh[1][j][threadIdx.x]; }
        g_part2[blockIdx.x * 2 * C + threadIdx.x] = a;
        g_part2[blockIdx.x * 2 * C + C + threadIdx.x] = a2;
    }
}

__global__ __launch_bounds__(256) void bn_final2(int n) {
    int lane = threadIdx.x & 31, w = threadIdx.x >> 5;
    float S = 0.f, S2 = 0.f;
    for (int b = w; b < 64; b += 8) {
        S  += g_part2[b * 2 * C + lane];
        S2 += g_part2[b * 2 * C + C + lane];
    }
    __shared__ float sh[2][8][C];
    sh[0][w][lane] = S; sh[1][w][lane] = S2;
    __syncthreads();
    if (threadIdx.x < C) {
        float a = 0.f, a2 = 0.f;
#pragma unroll
        for (int j = 0; j < 8; j++) { a += sh[0][j][threadIdx.x]; a2 += sh[1][j][threadIdx.x]; }
        float mean = a / (float)n;
        float var = a2 / (float)n - mean * mean;
        g_mean[threadIdx.x] = mean;
        g_rstd[threadIdx.x] = rsqrtf(var + EPSBN);
    }
}

// ---------------- BN apply + ELU + linear (8 voxels/warp-iter, fast ELU) ----------------
__global__ __launch_bounds__(256) void apply_kernel(
    const float* __restrict__ gamma, const float* __restrict__ beta,
    const float* __restrict__ Wlin, const float* __restrict__ blin,
    float* __restrict__ out, int n)
{
    __shared__ __align__(16) float ysm[8][8][C];
    int lane = threadIdx.x & 31, w = threadIdx.x >> 5;
    float m = g_mean[lane], rs = g_rstd[lane];
    float ga = gamma[lane], be = beta[lane];
    F2U blu; blu.f = make_float2(blin[lane], 0.f);

    ull wl[16];
    const ull* wp = (const ull*)(Wlin + lane * C);
#pragma unroll
    for (int p = 0; p < 16; p++) wl[p] = wp[p];

    for (int v8 = (blockIdx.x * 8 + w) * 8; v8 < n; v8 += gridDim.x * 64) {
#pragma unroll
        for (int qq = 0; qq < 8; qq++) {
            int v = v8 + qq;
            float o = (v < n) ? out[(size_t)v * C + lane] : 0.f;
            float t = fmaf((o - m) * rs, ga, be);
            ysm[w][qq][lane] = (t > 0.f) ? t : (__expf(t) - 1.f);
        }
        __syncwarp();
#pragma unroll
        for (int qq = 0; qq < 8; qq++) {
            int v = v8 + qq;
            if (v < n) {
                const ull* ys = (const ull*)ysm[w][qq];
                ull z2 = blu.u;
#pragma unroll
                for (int p = 0; p < 16; p++) z2 = fma2(ys[p], wl[p], z2);
                F2U r; r.u = z2;
                out[(size_t)v * C + lane] = r.f.x + r.f.y;
            }
        }
        __syncwarp();
    }
}

extern "C" void kernel_launch(void* const* d_in, const int* in_sizes, int n_in,
                              void* d_out, int out_size)
{
    const float* x     = (const float*)d_in[0];
    const int*   nbr   = (const int*)d_in[1];
    const float* Wc    = (const float*)d_in[2];
    const float* bc    = (const float*)d_in[3];
    const float* gamma = (const float*)d_in[4];
    const float* beta  = (const float*)d_in[5];
    const float* Wl    = (const float*)d_in[6];
    const float* bl    = (const float*)d_in[7];
    float* out = (float*)d_out;

    int n  = in_sizes[0] / C;
    int kt = in_sizes[1] / n;
    int wtot = in_sizes[2];

    int nb = (n + MB - 1) / MB;
    if (kt == KTAP && n <= MAXN && nb <= MAXBLK) {
        static int smem_set = 0;
        if (!smem_set) {
            cudaFuncSetAttribute(conv_mma<KTAP>,
                                 cudaFuncAttributeMaxDynamicSharedMemorySize, SMEM_SZ);
            smem_set = 1;
        }
        int cw = (n + 7) / 8;                          // warps for convert_x
        convert_x<<<(cw * 32 + 255) / 256, 256>>>(x, n);
        convert_w<<<(wtot + 255) / 256, 256>>>(Wc, wtot);
        conv_mma<KTAP><<<nb, CTHREADS, SMEM_SZ>>>(nbr, bc, out, n);
        bn_mid<<<64, 256>>>(nb);
        bn_final2<<<1, 256>>>(n);
    } else {
        transpose_w<<<(wtot + 255) / 256, 256>>>(Wc, wtot);
        conv_generic<<<(n + 127) / 128, 256>>>(x, nbr, bc, out, n, kt);
        bn_partial<<<512, 256>>>(out, n);
        bn_mid<<<64, 256>>>(512);
        bn_final2<<<1, 256>>>(n);
    }
    apply_kernel<<<1024, 256>>>(gamma, beta, Wl, bl, out, n);
}

// round 17
// speedup vs baseline: 1.3519x; 1.0580x over previous
#include <cuda_runtime.h>
#include <cuda_bf16.h>
#include <cstdint>

#define C 32
#define EPSBN 1e-5f
#define KTAP 125
#define MAXN 500000
#define MAXBLK 8192
#define NSTG 4
#define MB 128                 // voxels per block
#define CTHREADS 128           // 4 warps x 32 voxels

typedef unsigned long long ull;

// smem layout (bytes)
#define OFF_X   0                       // 4 stages x 16384 (x tiles, swizzled 128B rows)
#define OFF_W   65536                   // 4 stages x 4096  (W tiles)
#define OFF_RED 81920                   // 4 warps x 64 floats
#define OFF_Z   82944                   // 128B zero row for invalid-ldsm redirect
#define SMEM_SZ 83072

// ---- device scratch ----
__device__ __align__(16) unsigned char g_xhl[(size_t)MAXN * 128];  // [N][hi 64B | lo 64B]
__device__ __align__(16) unsigned char g_whl[KTAP * 4096];         // [K][cin][hi 64B | lo 64B]
__device__ __align__(16) float g_Wt[KTAP * C * C];                 // fallback
__device__ float g_part[MAXBLK * 2 * C];
__device__ float g_part2[64 * 2 * C];
__device__ float g_mean[C];
__device__ float g_rstd[C];

// ---- PTX helpers ----
__device__ __forceinline__ void cp_async16(uint32_t dst, const void* src) {
    asm volatile("cp.async.cg.shared.global [%0], [%1], 16;" :: "r"(dst), "l"(src));
}
__device__ __forceinline__ void cp_commit() { asm volatile("cp.async.commit_group;"); }
template <int N_> __device__ __forceinline__ void cp_wait() {
    asm volatile("cp.async.wait_group %0;" :: "n"(N_));
}
__device__ __forceinline__ void ldsm4(uint32_t* r, uint32_t a) {
    asm volatile("ldmatrix.sync.aligned.m8n8.x4.shared.b16 {%0,%1,%2,%3}, [%4];"
                 : "=r"(r[0]), "=r"(r[1]), "=r"(r[2]), "=r"(r[3]) : "r"(a));
}
__device__ __forceinline__ void ldsm4t(uint32_t* r, uint32_t a) {
    asm volatile("ldmatrix.sync.aligned.m8n8.x4.trans.shared.b16 {%0,%1,%2,%3}, [%4];"
                 : "=r"(r[0]), "=r"(r[1]), "=r"(r[2]), "=r"(r[3]) : "r"(a));
}
__device__ __forceinline__ void mma16816(float* c, const uint32_t* a, const uint32_t* b) {
    asm volatile("mma.sync.aligned.m16n8k16.row.col.f32.bf16.bf16.f32 "
                 "{%0,%1,%2,%3}, {%4,%5,%6,%7}, {%8,%9}, {%0,%1,%2,%3};"
                 : "+f"(c[0]), "+f"(c[1]), "+f"(c[2]), "+f"(c[3])
                 : "r"(a[0]), "r"(a[1]), "r"(a[2]), "r"(a[3]), "r"(b[0]), "r"(b[1]));
}
__device__ __forceinline__ ull fma2(ull a, ull b, ull c) {
    ull d; asm("fma.rn.f32x2 %0, %1, %2, %3;" : "=l"(d) : "l"(a), "l"(b), "l"(c)); return d;
}
union F2U { float2 f; ull u; };
union BF2U { __nv_bfloat162 b; uint32_t u; };

// ---------------- pre-convert x -> [hi|lo] bf16 rows (warp-cooperative, coalesced) ----------------
__global__ void convert_x(const float* __restrict__ x, int n) {
    int wg = (blockIdx.x * blockDim.x + threadIdx.x) >> 5;  // warp handles 8 rows
    int lane = threadIdx.x & 31;
    int r0 = wg * 8;
    if (r0 >= n) return;
    const float4* src = (const float4*)(x + (size_t)r0 * C);
#pragma unroll
    for (int h = 0; h < 2; h++) {
        int f = lane + h * 32;
        int row = r0 + (f >> 3), quad = f & 7;
        if (row < n) {
            float4 v = __ldg(src + f);
            __nv_bfloat16 h0 = __float2bfloat16(v.x), h1 = __float2bfloat16(v.y);
            __nv_bfloat16 h2 = __float2bfloat16(v.z), h3 = __float2bfloat16(v.w);
            BF2U hi0, hi1, lo0, lo1;
            hi0.b.x = h0; hi0.b.y = h1;
            hi1.b.x = h2; hi1.b.y = h3;
            lo0.b.x = __float2bfloat16(v.x - __bfloat162float(h0));
            lo0.b.y = __float2bfloat16(v.y - __bfloat162float(h1));
            lo1.b.x = __float2bfloat16(v.z - __bfloat162float(h2));
            lo1.b.y = __float2bfloat16(v.w - __bfloat162float(h3));
            unsigned char* dstrow = g_xhl + (size_t)row * 128;
            *(uint2*)(dstrow + quad * 8)      = make_uint2(hi0.u, hi1.u);
            *(uint2*)(dstrow + 64 + quad * 8) = make_uint2(lo0.u, lo1.u);
        }
    }
}

// ---------------- pre-convert W [K][CIN][COUT] -> [K][cin][hi|lo] ----------------
__global__ void convert_w(const float* __restrict__ W, int total) {
    int i = blockIdx.x * blockDim.x + threadIdx.x;
    if (i >= total) return;
    int k = i / (C * C), r = i % (C * C);
    int cin = r >> 5, cout = r & 31;
    float f = W[i];
    __nv_bfloat16 h = __float2bfloat16(f);
    __nv_bfloat16 l = __float2bfloat16(f - __bfloat162float(h));
    __nv_bfloat16* row = (__nv_bfloat16*)(g_whl + (size_t)k * 4096 + cin * 128);
    row[cout] = h;
    row[32 + cout] = l;
}

// ---------------- mma sparse conv (skip invalid gathers, ldsm zero-redirect) ----------------
template <int KT>
__global__ __launch_bounds__(CTHREADS, 2) void conv_mma(
    const int* __restrict__ nbr, const float* __restrict__ bconv,
    float* __restrict__ out, int n)
{
    extern __shared__ __align__(16) unsigned char smem[];
    const uint32_t sb = (uint32_t)__cvta_generic_to_shared(smem);
    const int tid = threadIdx.x, warp = tid >> 5, lane = tid & 31;
    const int vb = blockIdx.x * MB;
    const int vg = vb + tid;
    const bool vok = vg < n;
    const int q = lane >> 3, rl = lane & 7;
    const int g = lane >> 2, tq = lane & 3;
    const int* nrow = nbr + (size_t)(vok ? vg : 0) * KT;
    const uint32_t za = sb + OFF_Z;        // zero row for invalid ldsm lanes

    // zero the redirect row (published by the first in-loop barrier)
    if (tid < 32) ((float*)(smem + OFF_Z))[tid] = 0.f;

    float acc[2][4][4];
#pragma unroll
    for (int a = 0; a < 2; a++)
#pragma unroll
        for (int b = 0; b < 4; b++)
#pragma unroll
            for (int c = 0; c < 4; c++) acc[a][b][c] = 0.f;

    int nidx[NSTG];
    unsigned vmask[NSTG];

    auto FETCH = [&](int tt) {
        nidx[tt & 3] = vok ? __ldg(nrow + tt) : -1;
    };
    auto ISSUE = [&](int tt) {
        int s = tt & 3;
        int id = nidx[s];
        vmask[s] = __ballot_sync(0xffffffffu, id >= 0);
        if (id >= 0) {
            const unsigned char* src = g_xhl + (size_t)id * 128;
            uint32_t xdst = sb + OFF_X + s * 16384 + tid * 128;
#pragma unroll
            for (int j = 0; j < 8; j++)
                cp_async16(xdst + (uint32_t)(((j ^ (lane & 7)) << 4)), src + j * 16);
        }
#pragma unroll
        for (int h = 0; h < 2; h++) {
            int cc = tid + h * 128;
            int row = cc >> 3, jj = cc & 7;
            cp_async16(sb + OFF_W + s * 4096 + row * 128 + (uint32_t)(((jj ^ (row & 7)) << 4)),
                       g_whl + (size_t)tt * 4096 + cc * 16);
        }
    };
    auto COMPUTE = [&](int tt) {
        int s = tt & 3;
        uint32_t xb = sb + OFF_X + s * 16384;
        uint32_t wb = sb + OFF_W + s * 4096;
        unsigned vm = vmask[s];
        uint32_t wf[2][2][4][2];
#pragma unroll
        for (int part = 0; part < 2; part++)
#pragma unroll
            for (int ks = 0; ks < 2; ks++)
#pragma unroll
                for (int np = 0; np < 2; np++) {
                    int row = ks * 16 + (q & 1) * 8 + rl;
                    int jj = part * 4 + np * 2 + (q >> 1);
                    uint32_t r4[4];
                    ldsm4t(r4, wb + row * 128 + (uint32_t)(((jj ^ (row & 7)) << 4)));
                    wf[part][ks][np * 2][0] = r4[0]; wf[part][ks][np * 2][1] = r4[1];
                    wf[part][ks][np * 2 + 1][0] = r4[2]; wf[part][ks][np * 2 + 1][1] = r4[3];
                }
#pragma unroll
        for (int mt = 0; mt < 2; mt++) {
            int rloc = mt * 16 + (q & 1) * 8 + rl;       // row within this warp's 32
            int rowa = warp * 32 + rloc;
            bool rv = (vm >> rloc) & 1u;
            uint32_t rb = xb + rowa * 128;
            uint32_t ah[2][4], al[2][4];
#pragma unroll
            for (int ks = 0; ks < 2; ks++) {
                int c0 = ks * 2 + (q >> 1);
                uint32_t a = rv ? rb + (uint32_t)(((c0 ^ (rowa & 7)) << 4)) : za;
                ldsm4(ah[ks], a);
            }
#pragma unroll
            for (int ks = 0; ks < 2; ks++) {
                int c0 = 4 + ks * 2 + (q >> 1);
                uint32_t a = rv ? rb + (uint32_t)(((c0 ^ (rowa & 7)) << 4)) : za;
                ldsm4(al[ks], a);
            }
#pragma unroll
            for (int nt = 0; nt < 4; nt++) {
                mma16816(acc[mt][nt], ah[0], wf[0][0][nt]);   // hi*hi k0-15
                mma16816(acc[mt][nt], ah[1], wf[0][1][nt]);   // hi*hi k16-31
                mma16816(acc[mt][nt], ah[0], wf[1][0][nt]);   // hi*lo
                mma16816(acc[mt][nt], ah[1], wf[1][1][nt]);
                mma16816(acc[mt][nt], al[0], wf[0][0][nt]);   // lo*hi
                mma16816(acc[mt][nt], al[1], wf[0][1][nt]);
            }
        }
    };

    // prologue: interleaved so FETCH(t+4) never clobbers a slot before ISSUE(t) reads it
    FETCH(0); FETCH(1); FETCH(2); FETCH(3);
    ISSUE(0); cp_commit();
    FETCH(4); ISSUE(1); cp_commit();
    FETCH(5); ISSUE(2); cp_commit();

#pragma unroll 4
    for (int t = 0; t < KT; t++) {
        if (t + 6 < KT) FETCH(t + 6);
        cp_wait<2>();
        __syncthreads();
        COMPUTE(t);
        if (t + 3 < KT) ISSUE(t + 3);
        cp_commit();
    }

    // ---- epilogue: bias + store + fused BN partials from fragments ----
    float2 bp[4];
#pragma unroll
    for (int nt = 0; nt < 4; nt++)
        bp[nt] = *(const float2*)(bconv + nt * 8 + 2 * tq);

    float s1[4][2], s2[4][2];
#pragma unroll
    for (int nt = 0; nt < 4; nt++) { s1[nt][0] = s1[nt][1] = s2[nt][0] = s2[nt][1] = 0.f; }

#pragma unroll
    for (int mt = 0; mt < 2; mt++) {
        int r0 = warp * 32 + mt * 16 + g;
        int r1 = r0 + 8;
        bool ok0 = (vb + r0) < n, ok1 = (vb + r1) < n;
#pragma unroll
        for (int nt = 0; nt < 4; nt++) {
            if (ok0) {
                float y0 = acc[mt][nt][0] + bp[nt].x;
                float y1 = acc[mt][nt][1] + bp[nt].y;
                *(float2*)(out + (size_t)(vb + r0) * C + nt * 8 + 2 * tq) = make_float2(y0, y1);
                s1[nt][0] += y0; s1[nt][1] += y1;
                s2[nt][0] += y0 * y0; s2[nt][1] += y1 * y1;
            }
            if (ok1) {
                float y0 = acc[mt][nt][2] + bp[nt].x;
                float y1 = acc[mt][nt][3] + bp[nt].y;
                *(float2*)(out + (size_t)(vb + r1) * C + nt * 8 + 2 * tq) = make_float2(y0, y1);
                s1[nt][0] += y0; s1[nt][1] += y1;
                s2[nt][0] += y0 * y0; s2[nt][1] += y1 * y1;
            }
        }
    }
#pragma unroll
    for (int nt = 0; nt < 4; nt++)
#pragma unroll
        for (int e = 0; e < 2; e++) {
#pragma unroll
            for (int msk = 4; msk < 32; msk <<= 1) {
                s1[nt][e] += __shfl_xor_sync(0xffffffffu, s1[nt][e], msk);
                s2[nt][e] += __shfl_xor_sync(0xffffffffu, s2[nt][e], msk);
            }
        }
    float* red = (float*)(smem + OFF_RED);
    if (lane < 4) {
#pragma unroll
        for (int nt = 0; nt < 4; nt++)
#pragma unroll
            for (int e = 0; e < 2; e++) {
                int col = nt * 8 + 2 * tq + e;
                red[warp * 64 + col] = s1[nt][e];
                red[warp * 64 + 32 + col] = s2[nt][e];
            }
    }
    __syncthreads();
    if (tid < C) {
        float a = 0.f, b = 0.f;
#pragma unroll
        for (int w = 0; w < 4; w++) { a += red[w * 64 + tid]; b += red[w * 64 + 32 + tid]; }
        g_part[blockIdx.x * 2 * C + tid] = a;
        g_part[blockIdx.x * 2 * C + C + tid] = b;
    }
}

// ---------------- fallback path ----------------
__global__ void transpose_w(const float* __restrict__ W, int total) {
    int i = blockIdx.x * blockDim.x + threadIdx.x;
    if (i < total) {
        int k = i / (C * C), r = i % (C * C);
        int cin = r / C, cout = r % C;
        g_Wt[k * C * C + cout * C + cin] = W[i];
    }
}

__global__ __launch_bounds__(256) void conv_generic(
    const float* __restrict__ x, const int* __restrict__ nbr,
    const float* __restrict__ bconv, float* __restrict__ out,
    int n, int kt)
{
    __shared__ __align__(16) float xsm[8][16][C];
    int warp = threadIdx.x >> 5, lane = threadIdx.x & 31;
    int v0 = blockIdx.x * 128 + warp * 16;
    float b = bconv[lane];
    float acc[16];
#pragma unroll
    for (int i = 0; i < 16; i++) acc[i] = b;
    for (int k = 0; k < kt; k++) {
        float4 w[8];
        const float4* wp = (const float4*)(g_Wt + k * C * C + lane * C);
#pragma unroll
        for (int j = 0; j < 8; j++) w[j] = wp[j];
        unsigned vm = 0;
#pragma unroll
        for (int i = 0; i < 16; i++) {
            int v = v0 + i;
            if (v < n) {
                int idx = __ldg(&nbr[(size_t)v * kt + k]);
                if (idx >= 0) { vm |= (1u << i); xsm[warp][i][lane] = x[(size_t)idx * C + lane]; }
            }
        }
        __syncwarp();
#pragma unroll
        for (int i = 0; i < 16; i++) {
            if ((vm >> i) & 1u) {
                const float4* xs = (const float4*)xsm[warp][i];
                float a = acc[i];
#pragma unroll
                for (int j = 0; j < 8; j++) {
                    float4 xv = xs[j];
                    a = fmaf(xv.x, w[j].x, a); a = fmaf(xv.y, w[j].y, a);
                    a = fmaf(xv.z, w[j].z, a); a = fmaf(xv.w, w[j].w, a);
                }
                acc[i] = a;
            }
        }
        __syncwarp();
    }
#pragma unroll
    for (int i = 0; i < 16; i++) {
        int v = v0 + i;
        if (v < n) out[(size_t)v * C + lane] = acc[i];
    }
}

__global__ __launch_bounds__(256) void bn_partial(const float* __restrict__ out, int n) {
    int lane = threadIdx.x & 31, w = threadIdx.x >> 5;
    float s = 0.f, s2 = 0.f;
    for (int r = blockIdx.x * 8 + w; r < n; r += gridDim.x * 8) {
        float v = out[(size_t)r * C + lane];
        s += v; s2 += v * v;
    }
    __shared__ float sh[2][8][C];
    sh[0][w][lane] = s; sh[1][w][lane] = s2;
    __syncthreads();
    if (threadIdx.x < C) {
        float S = 0.f, S2 = 0.f;
#pragma unroll
        for (int j = 0; j < 8; j++) { S += sh[0][j][threadIdx.x]; S2 += sh[1][j][threadIdx.x]; }
        g_part[blockIdx.x * 2 * C + threadIdx.x] = S;
        g_part[blockIdx.x * 2 * C + C + threadIdx.x] = S2;
    }
}

__global__ __launch_bounds__(256) void bn_mid(int nblocks) {
    int lane = threadIdx.x & 31, w = threadIdx.x >> 5;
    float S = 0.f, S2 = 0.f;
    for (int b = blockIdx.x + w * 64; b < nblocks; b += 512) {
        S  += g_part[b * 2 * C + lane];
        S2 += g_part[b * 2 * C + C + lane];
    }
    __shared__ float sh[2][8][C];
    sh[0][w][lane] = S; sh[1][w][lane] = S2;
    __syncthreads();
    if (threadIdx.x < C) {
        float a = 0.f, a2 = 0.f;
#pragma unroll
        for (int j = 0; j < 8; j++) { a += sh[0][j][threadIdx.x]; a2 += sh[1][j][threadIdx.x]; }
        g_part2[blockIdx.x * 2 * C + threadIdx.x] = a;
        g_part2[blockIdx.x * 2 * C + C + threadIdx.x] = a2;
    }
}

__global__ __launch_bounds__(256) void bn_final2(int n) {
    int lane = threadIdx.x & 31, w = threadIdx.x >> 5;
    float S = 0.f, S2 = 0.f;
    for (int b = w; b < 64; b += 8) {
        S  += g_part2[b * 2 * C + lane];
        S2 += g_part2[b * 2 * C + C + lane];
    }
    __shared__ float sh[2][8][C];
    sh[0][w][lane] = S; sh[1][w][lane] = S2;
    __syncthreads();
    if (threadIdx.x < C) {
        float a = 0.f, a2 = 0.f;
#pragma unroll
        for (int j = 0; j < 8; j++) { a += sh[0][j][threadIdx.x]; a2 += sh[1][j][threadIdx.x]; }
        float mean = a / (float)n;
        float var = a2 / (float)n - mean * mean;
        g_mean[threadIdx.x] = mean;
        g_rstd[threadIdx.x] = rsqrtf(var + EPSBN);
    }
}

// ---------------- BN apply + ELU + linear (8 voxels/warp-iter, fast ELU) ----------------
__global__ __launch_bounds__(256) void apply_kernel(
    const float* __restrict__ gamma, const float* __restrict__ beta,
    const float* __restrict__ Wlin, const float* __restrict__ blin,
    float* __restrict__ out, int n)
{
    __shared__ __align__(16) float ysm[8][8][C];
    int lane = threadIdx.x & 31, w = threadIdx.x >> 5;
    float m = g_mean[lane], rs = g_rstd[lane];
    float ga = gamma[lane], be = beta[lane];
    F2U blu; blu.f = make_float2(blin[lane], 0.f);

    ull wl[16];
    const ull* wp = (const ull*)(Wlin + lane * C);
#pragma unroll
    for (int p = 0; p < 16; p++) wl[p] = wp[p];

    for (int v8 = (blockIdx.x * 8 + w) * 8; v8 < n; v8 += gridDim.x * 64) {
#pragma unroll
        for (int qq = 0; qq < 8; qq++) {
            int v = v8 + qq;
            float o = (v < n) ? out[(size_t)v * C + lane] : 0.f;
            float t = fmaf((o - m) * rs, ga, be);
            ysm[w][qq][lane] = (t > 0.f) ? t : (__expf(t) - 1.f);
        }
        __syncwarp();
#pragma unroll
        for (int qq = 0; qq < 8; qq++) {
            int v = v8 + qq;
            if (v < n) {
                const ull* ys = (const ull*)ysm[w][qq];
                ull z2 = blu.u;
#pragma unroll
                for (int p = 0; p < 16; p++) z2 = fma2(ys[p], wl[p], z2);
                F2U r; r.u = z2;
                out[(size_t)v * C + lane] = r.f.x + r.f.y;
            }
        }
        __syncwarp();
    }
}

extern "C" void kernel_launch(void* const* d_in, const int* in_sizes, int n_in,
                              void* d_out, int out_size)
{
    const float* x     = (const float*)d_in[0];
    const int*   nbr   = (const int*)d_in[1];
    const float* Wc    = (const float*)d_in[2];
    const float* bc    = (const float*)d_in[3];
    const float* gamma = (const float*)d_in[4];
    const float* beta  = (const float*)d_in[5];
    const float* Wl    = (const float*)d_in[6];
    const float* bl    = (const float*)d_in[7];
    float* out = (float*)d_out;

    int n  = in_sizes[0] / C;
    int kt = in_sizes[1] / n;
    int wtot = in_sizes[2];

    int nb = (n + MB - 1) / MB;
    if (kt == KTAP && n <= MAXN && nb <= MAXBLK) {
        static int smem_set = 0;
        if (!smem_set) {
            cudaFuncSetAttribute(conv_mma<KTAP>,
                                 cudaFuncAttributeMaxDynamicSharedMemorySize, SMEM_SZ);
            smem_set = 1;
        }
        int cw = (n + 7) / 8;
        convert_x<<<(cw * 32 + 255) / 256, 256>>>(x, n);
        convert_w<<<(wtot + 255) / 256, 256>>>(Wc, wtot);
        conv_mma<KTAP><<<nb, CTHREADS, SMEM_SZ>>>(nbr, bc, out, n);
        bn_mid<<<64, 256>>>(nb);
        bn_final2<<<1, 256>>>(n);
    } else {
        transpose_w<<<(wtot + 255) / 256, 256>>>(Wc, wtot);
        conv_generic<<<(n + 127) / 128, 256>>>(x, nbr, bc, out, n, kt);
        bn_partial<<<512, 256>>>(out, n);
        bn_mid<<<64, 256>>>(512);
        bn_final2<<<1, 256>>>(n);
    }
    apply_kernel<<<1024, 256>>>(gamma, beta, Wl, bl, out, n);
}